// round 9
// baseline (speedup 1.0000x reference)
#include <cuda_runtime.h>

#define KK 16
#define LL 64
#define BB 32768
#define ROWF4 256          // 256 float4 per element row
#define NPAIR (LL / 2)     // 32 digit pairs

typedef unsigned long long u64t;

__device__ __forceinline__ u64t pk2(float lo, float hi) {
    u64t r; asm("mov.b64 %0, {%1, %2};" : "=l"(r) : "f"(lo), "f"(hi)); return r;
}
__device__ __forceinline__ void upk2(float& lo, float& hi, u64t v) {
    asm("mov.b64 {%0, %1}, %2;" : "=f"(lo), "=f"(hi) : "l"(v));
}
__device__ __forceinline__ u64t fma2(u64t a, u64t b, u64t c) {
    u64t d; asm("fma.rn.f32x2 %0, %1, %2, %3;" : "=l"(d) : "l"(a), "l"(b), "l"(c)); return d;
}
__device__ __forceinline__ u64t add2(u64t a, u64t b) {
    u64t d; asm("add.rn.f32x2 %0, %1, %2;" : "=l"(d) : "l"(a), "l"(b)); return d;
}
__device__ __forceinline__ void cp16(unsigned dst, const float4* src) {
    asm volatile("cp.async.cg.shared.global [%0], [%1], 16;\n" :: "r"(dst), "l"(src));
}

// One warp per block, 32 elements per warp.
// Lane = (role, pi): role = ln>>4 (0 add, 1 sub), pi = ln&15.
// Each lane processes elements (pi, pi+16) PACKED in f32x2 for one role.
__global__ __launch_bounds__(32) void bitop_kernel(
    const float4* __restrict__ op1, const float4* __restrict__ op2,
    float4* __restrict__ outa, float4* __restrict__ outs)
{
    // input staging: rows 0-31 = op1 elems 0-31, rows 32-63 = op2 elems 0-31
    __shared__ float4 sin[2][64][9];
    // output staging: rows 0-31 = outa elems, rows 32-63 = outs elems
    __shared__ float4 sou[64][9];

    const int ln   = threadIdx.x;
    const int role = ln >> 4;
    const int pi   = ln & 15;
    const int ebase = blockIdx.x * 32;

    const int q = ln & 7;    // 16B slot in 128B pair chunk
    const int g = ln >> 3;   // 0..3

    unsigned sb[2];
    sb[0] = (unsigned)__cvta_generic_to_shared(&sin[0][0][0]);
    sb[1] = (unsigned)__cvta_generic_to_shared(&sin[1][0][0]);

    // staging: 16 rows per lane (g+4r), row<32 -> op1, else op2
    #define STAGE(b, p)                                                       \
        do {                                                                  \
            _Pragma("unroll")                                                 \
            for (int r = 0; r < 16; ++r) {                                    \
                const int row = g + 4 * r;                                    \
                const float4* src = ((row < 32) ? op1 : op2)                  \
                    + (size_t)(ebase + (row & 31)) * ROWF4                    \
                    + (size_t)(p) * 8 + q;                                    \
                cp16(sb[b] + row * 144 + q * 16, src);                        \
            }                                                                 \
            asm volatile("cp.async.commit_group;\n" ::);                      \
        } while (0)

    STAGE(0, 0);

    const u64t neg1 = pk2(-1.f, -1.f);
    const u64t one2 = pk2(1.f, 1.f);
    u64t t2 = role ? one2 : 0ull;   // carry1 (add) / borrow0 (sub), packed
    int buf = 0;

    #pragma unroll 1
    for (int p = 0; p < NPAIR; ++p) {
        if (p < NPAIR - 1) {
            STAGE(buf ^ 1, p + 1);
            asm volatile("cp.async.wait_group 1;\n" ::);
        } else {
            asm volatile("cp.async.wait_group 0;\n" ::);
        }
        __syncwarp();

        #pragma unroll 1
        for (int d = 0; d < 2; ++d) {
            const int s = d * 4;

            // load both elements' digit (a from op1, c from op2)
            float4 A1[4], A2[4], C1[4], C2[4];
            #pragma unroll
            for (int w = 0; w < 4; ++w) {
                A1[w] = sin[buf][pi][s + w];
                A2[w] = sin[buf][pi + 16][s + w];
                C1[w] = sin[buf][32 + pi][s + w];
                C2[w] = sin[buf][48 + pi][s + w];
            }

            // pack element pairs
            u64t ap[16], cp_[16];
            #pragma unroll
            for (int w = 0; w < 4; ++w) {
                const float* a1 = &A1[w].x; const float* a2 = &A2[w].x;
                const float* c1 = &C1[w].x; const float* c2 = &C2[w].x;
                #pragma unroll
                for (int u = 0; u < 4; ++u) {
                    ap[4 * w + u]  = pk2(a1[u], a2[u]);
                    cp_[4 * w + u] = pk2(c1[u], c2[u]);
                }
            }

            // suffix sums of c (packed)
            u64t Cs[16];
            Cs[15] = cp_[15];
            #pragma unroll
            for (int m = 14; m >= 1; --m) Cs[m] = add2(Cs[m + 1], cp_[m]);

            // both side-sums (cheaper than packed selects)
            u64t Sa = 0ull, Ss = 0ull;
            #pragma unroll
            for (int i = 1; i < 16; ++i)  Sa = fma2(ap[i], Cs[16 - i], Sa); // P(i+j>=16)
            #pragma unroll
            for (int i = 0; i < 15; ++i)  Ss = fma2(ap[i], Cs[i + 1], Ss);  // P(i<j)

            // sub lanes: reverse c in place (role-uniform selects)
            #pragma unroll
            for (int j = 0; j < 8; ++j) {
                const u64t lo = cp_[j], hi = cp_[15 - j];
                cp_[j]      = role ? hi : lo;
                cp_[15 - j] = role ? lo : hi;
            }

            // packed cyclic convolution: 256 fma2 covering 2 elements
            u64t X[16];
            #pragma unroll
            for (int v = 0; v < 16; ++v) X[v] = 0ull;
            #pragma unroll
            for (int i = 0; i < 16; ++i) {
                #pragma unroll
                for (int j = 0; j < 16; ++j)
                    X[(i + j) & 15] = fma2(ap[i], cp_[j], X[(i + j) & 15]);
            }

            // res[v] = X[v] + t * (X[v-1] - X[v])
            u64t R[16];
            #pragma unroll
            for (int v = 0; v < 16; ++v) {
                const u64t delta = fma2(neg1, X[v], X[(v + 15) & 15]);
                R[v] = fma2(t2, delta, X[v]);
            }

            // state: t' = base + t * X[15]
            const u64t base_add = Sa;
            const u64t base_sub = fma2(neg1, add2(Ss, X[15]), one2);
            t2 = fma2(t2, X[15], role ? base_sub : base_add);

            // unpack & stage outputs: lo half -> elem pi, hi half -> elem pi+16
            float rl[16], rh[16];
            #pragma unroll
            for (int v = 0; v < 16; ++v) upk2(rl[v], rh[v], R[v]);

            const int rb = role * 32 + pi;
            #pragma unroll
            for (int w = 0; w < 4; ++w) {
                sou[rb][s + w]      = make_float4(rl[4*w], rl[4*w+1], rl[4*w+2], rl[4*w+3]);
                sou[rb + 16][s + w] = make_float4(rh[4*w], rh[4*w+1], rh[4*w+2], rh[4*w+3]);
            }
        }
        __syncwarp();

        // full-128B coalesced stores: 16 rows per lane
        #pragma unroll
        for (int r = 0; r < 16; ++r) {
            const int row = g + 4 * r;
            float4* dst = ((row < 32) ? outa : outs)
                + (size_t)(ebase + (row & 31)) * ROWF4 + (size_t)p * 8 + q;
            *dst = sou[row][q];
        }
        __syncwarp();   // sou/sin reads complete before next pair overwrites

        buf ^= 1;
    }
    #undef STAGE
}

extern "C" void kernel_launch(void* const* d_in, const int* in_sizes, int n_in,
                              void* d_out, int out_size)
{
    const float4* op1 = (const float4*)d_in[0];
    const float4* op2 = (const float4*)d_in[1];
    float* out = (float*)d_out;
    float4* outa = (float4*)out;
    float4* outs = (float4*)(out + (size_t)BB * LL * KK);

    bitop_kernel<<<BB / 32, 32>>>(op1, op2, outa, outs);
}

// round 10
// speedup vs baseline: 1.0498x; 1.0498x over previous
#include <cuda_runtime.h>

#define KK 16
#define LL 64
#define BB 32768
#define ROWF4 256          // 256 float4 per element row
#define NPAIR (LL / 2)     // 32 digit pairs

__device__ __forceinline__ void cp16(unsigned dst, const float4* src) {
    asm volatile("cp.async.cg.shared.global [%0], [%1], 16;\n" :: "r"(dst), "l"(src));
}

// Per-digit math, ROLE compile-time: 0 = add (carry1 state), 1 = sub (borrow0 state).
// For ROLE 1 the c array is built REVERSED at unpack (free), so both roles share
// the identical cyclic-convolution / res / state code shape.
template<int ROLE>
__device__ __forceinline__ void digit_math(
    const float4* __restrict__ Ain,   // 4 slots of a
    const float4* __restrict__ Cin,   // 4 slots of c (original order in smem)
    float& t, float4* __restrict__ so)
{
    float a[16], c[16];
    #pragma unroll
    for (int w = 0; w < 4; ++w) {
        const float4 A = Ain[w], C = Cin[w];
        a[4*w+0] = A.x; a[4*w+1] = A.y; a[4*w+2] = A.z; a[4*w+3] = A.w;
        if (ROLE == 0) {
            c[4*w+0] = C.x; c[4*w+1] = C.y; c[4*w+2] = C.z; c[4*w+3] = C.w;
        } else {  // reversed: c'[j] = c_orig[15-j]
            c[15-(4*w+0)] = C.x; c[15-(4*w+1)] = C.y;
            c[15-(4*w+2)] = C.z; c[15-(4*w+3)] = C.w;
        }
    }

    // S for add: P(i+j>=16) via suffix sums of working c.
    // S for sub: P(i<j) = sum_i a_i * Cpre'[14-i] via prefix sums of reversed c.
    float S = 0.f;
    if (ROLE == 0) {
        float Cs[16];
        Cs[15] = c[15];
        #pragma unroll
        for (int m = 14; m >= 1; --m) Cs[m] = Cs[m + 1] + c[m];
        #pragma unroll
        for (int i = 1; i < 16; ++i) S = fmaf(a[i], Cs[16 - i], S);
    } else {
        float Cp[15];
        Cp[0] = c[0];
        #pragma unroll
        for (int m = 1; m < 15; ++m) Cp[m] = Cp[m - 1] + c[m];
        #pragma unroll
        for (int i = 0; i < 15; ++i) S = fmaf(a[i], Cp[14 - i], S);
    }

    // shared cyclic convolution (256 FMA)
    float X[16];
    #pragma unroll
    for (int v = 0; v < 16; ++v) X[v] = 0.f;
    #pragma unroll
    for (int i = 0; i < 16; ++i) {
        #pragma unroll
        for (int j = 0; j < 16; ++j)
            X[(i + j) & 15] = fmaf(a[i], c[j], X[(i + j) & 15]);
    }

    // res[v] = (1-t)*X[v] + t*X[(v-1)&15]
    float r[16];
    #pragma unroll
    for (int v = 0; v < 16; ++v)
        r[v] = fmaf(t, X[(v + 15) & 15] - X[v], X[v]);

    // state: t' = base + t * X[15]
    const float base = (ROLE == 0) ? S : (1.f - S - X[15]);
    t = fmaf(t, X[15], base);

    #pragma unroll
    for (int w = 0; w < 4; ++w)
        so[w] = make_float4(r[4*w], r[4*w+1], r[4*w+2], r[4*w+3]);
}

// Block = 64 threads: warp 0 = add role, warp 1 = sub role, 32 shared elements.
__global__ __launch_bounds__(64) void bitop_kernel(
    const float4* __restrict__ op1, const float4* __restrict__ op2,
    float4* __restrict__ outa, float4* __restrict__ outs)
{
    // input staging: rows 0-31 = op1 elems, rows 32-63 = op2 elems; 8 slots + pad
    __shared__ float4 sin[2][64][9];
    // per-warp output staging
    __shared__ float4 sou[2][32][9];

    const int tid = threadIdx.x;
    const int wid = tid >> 5;      // 0 = add, 1 = sub
    const int ln  = tid & 31;      // element index within block
    const int ebase = blockIdx.x * 32;

    // cooperative staging role (all 64 threads): 8 rows each
    const int q8 = tid & 7;        // 16B slot
    const int g8 = tid >> 3;       // 0..7

    unsigned sb[2];
    sb[0] = (unsigned)__cvta_generic_to_shared(&sin[0][0][0]);
    sb[1] = (unsigned)__cvta_generic_to_shared(&sin[1][0][0]);

    #define STAGE(b, p)                                                       \
        do {                                                                  \
            _Pragma("unroll")                                                 \
            for (int r = 0; r < 8; ++r) {                                     \
                const int row = g8 + 8 * r;                                   \
                const float4* src = ((row < 32) ? op1 : op2)                  \
                    + (size_t)(ebase + (row & 31)) * ROWF4                    \
                    + (size_t)(p) * 8 + q8;                                   \
                cp16(sb[b] + row * 144 + q8 * 16, src);                       \
            }                                                                 \
            asm volatile("cp.async.commit_group;\n" ::);                      \
        } while (0)

    STAGE(0, 0);

    // store role (per warp): lane covers rows g4+4r, slot q4, of its own tensor
    const int q4 = ln & 7;
    const int g4 = ln >> 3;        // 0..3
    float4* const optr = wid ? outs : outa;

    float t = wid ? 1.f : 0.f;     // carry1 (add) / borrow0 (sub)
    int buf = 0;

    #pragma unroll 1
    for (int p = 0; p < NPAIR; ++p) {
        if (p < NPAIR - 1) {
            STAGE(buf ^ 1, p + 1);
            asm volatile("cp.async.wait_group 1;\n" ::);
        } else {
            asm volatile("cp.async.wait_group 0;\n" ::);
        }
        __syncthreads();   // pair p data visible to all threads

        // two digits of this pair
        #pragma unroll 1
        for (int d = 0; d < 2; ++d) {
            const int s = d * 4;
            if (wid == 0)
                digit_math<0>(&sin[buf][ln][s], &sin[buf][32 + ln][s], t,
                              &sou[0][ln][s]);
            else
                digit_math<1>(&sin[buf][ln][s], &sin[buf][32 + ln][s], t,
                              &sou[1][ln][s]);
        }
        __syncwarp();      // own warp's sou rows complete

        // full-128B coalesced stores of this warp's output tensor
        #pragma unroll
        for (int r = 0; r < 8; ++r) {
            const int row = g4 + 4 * r;
            optr[(size_t)(ebase + row) * ROWF4 + (size_t)p * 8 + q4]
                = sou[wid][row][q4];
        }

        __syncthreads();   // all reads of sin[buf] done before restaging it
        buf ^= 1;
    }
    #undef STAGE
}

extern "C" void kernel_launch(void* const* d_in, const int* in_sizes, int n_in,
                              void* d_out, int out_size)
{
    const float4* op1 = (const float4*)d_in[0];
    const float4* op2 = (const float4*)d_in[1];
    float* out = (float*)d_out;
    float4* outa = (float4*)out;
    float4* outs = (float4*)(out + (size_t)BB * LL * KK);

    bitop_kernel<<<BB / 32, 64>>>(op1, op2, outa, outs);
}

// round 11
// speedup vs baseline: 1.1550x; 1.1002x over previous
#include <cuda_runtime.h>

#define KK 16
#define LL 64
#define BB 32768
#define ROWF4 256          // 256 float4 per element row
#define NPAIR (LL / 2)     // 32 digit pairs

__device__ __forceinline__ void cp16(unsigned dst, const float4* src) {
    asm volatile("cp.async.cg.shared.global [%0], [%1], 16;\n" :: "r"(dst), "l"(src));
}

// ROLE 0 = add (carry1 state), ROLE 1 = sub (borrow0 state, c reversed at unpack).
template<int ROLE>
__device__ __forceinline__ void digit_math(
    const float4 Ain[4], const float4 Cin[4],
    float& t, float4* __restrict__ so)
{
    float a[16], c[16];
    #pragma unroll
    for (int w = 0; w < 4; ++w) {
        const float4 A = Ain[w], C = Cin[w];
        a[4*w+0] = A.x; a[4*w+1] = A.y; a[4*w+2] = A.z; a[4*w+3] = A.w;
        if (ROLE == 0) {
            c[4*w+0] = C.x; c[4*w+1] = C.y; c[4*w+2] = C.z; c[4*w+3] = C.w;
        } else {  // c'[j] = c_orig[15-j], free register renaming
            c[15-(4*w+0)] = C.x; c[15-(4*w+1)] = C.y;
            c[15-(4*w+2)] = C.z; c[15-(4*w+3)] = C.w;
        }
    }

    // S: add = P(i+j>=16) via suffix sums; sub = P(i<j) via prefix sums of reversed c
    float S = 0.f;
    if (ROLE == 0) {
        float Cs[16];
        Cs[15] = c[15];
        #pragma unroll
        for (int m = 14; m >= 1; --m) Cs[m] = Cs[m + 1] + c[m];
        #pragma unroll
        for (int i = 1; i < 16; ++i) S = fmaf(a[i], Cs[16 - i], S);
    } else {
        float Cp[15];
        Cp[0] = c[0];
        #pragma unroll
        for (int m = 1; m < 15; ++m) Cp[m] = Cp[m - 1] + c[m];
        #pragma unroll
        for (int i = 0; i < 15; ++i) S = fmaf(a[i], Cp[14 - i], S);
    }

    // shared cyclic convolution (256 FMA)
    float X[16];
    #pragma unroll
    for (int v = 0; v < 16; ++v) X[v] = 0.f;
    #pragma unroll
    for (int i = 0; i < 16; ++i) {
        #pragma unroll
        for (int j = 0; j < 16; ++j)
            X[(i + j) & 15] = fmaf(a[i], c[j], X[(i + j) & 15]);
    }

    // res[v] = (1-t)*X[v] + t*X[(v-1)&15]
    float r[16];
    #pragma unroll
    for (int v = 0; v < 16; ++v)
        r[v] = fmaf(t, X[(v + 15) & 15] - X[v], X[v]);

    const float base = (ROLE == 0) ? S : (1.f - S - X[15]);
    t = fmaf(t, X[15], base);

    #pragma unroll
    for (int w = 0; w < 4; ++w)
        so[w] = make_float4(r[4*w], r[4*w+1], r[4*w+2], r[4*w+3]);
}

// Block = 64 threads: warp 0 = add, warp 1 = sub, 32 shared elements.
// Register-pipelined: smem reads for digit d+1 issued before computing digit d.
__global__ __launch_bounds__(64) void bitop_kernel(
    const float4* __restrict__ op1, const float4* __restrict__ op2,
    float4* __restrict__ outa, float4* __restrict__ outs)
{
    __shared__ float4 sin[2][64][9];   // rows 0-31 op1, 32-63 op2
    __shared__ float4 sou[2][32][9];

    const int tid = threadIdx.x;
    const int wid = tid >> 5;      // 0 = add, 1 = sub
    const int ln  = tid & 31;
    const int ebase = blockIdx.x * 32;

    const int q8 = tid & 7;
    const int g8 = tid >> 3;

    unsigned sb[2];
    sb[0] = (unsigned)__cvta_generic_to_shared(&sin[0][0][0]);
    sb[1] = (unsigned)__cvta_generic_to_shared(&sin[1][0][0]);

    #define STAGE(b, p)                                                       \
        do {                                                                  \
            _Pragma("unroll")                                                 \
            for (int r = 0; r < 8; ++r) {                                     \
                const int row = g8 + 8 * r;                                   \
                const float4* src = ((row < 32) ? op1 : op2)                  \
                    + (size_t)(ebase + (row & 31)) * ROWF4                    \
                    + (size_t)(p) * 8 + q8;                                   \
                cp16(sb[b] + row * 144 + q8 * 16, src);                       \
            }                                                                 \
            asm volatile("cp.async.commit_group;\n" ::);                      \
        } while (0)

    // prologue: pair 0 staged & loaded to regs; pair 1 in flight
    STAGE(0, 0);
    asm volatile("cp.async.wait_group 0;\n" ::);
    __syncthreads();

    float4 A1[4], C1[4], A2[4], C2[4];
    #pragma unroll
    for (int w = 0; w < 4; ++w) {
        A1[w] = sin[0][ln][w];
        C1[w] = sin[0][32 + ln][w];
    }
    STAGE(1, 1);

    // store role: lane covers rows g4+4r, slot q4 of its own tensor
    const int q4 = ln & 7;
    const int g4 = ln >> 3;
    float4* const optr = wid ? outs : outa;
    const size_t obase[4] = {
        (size_t)(ebase + g4)      * ROWF4, (size_t)(ebase + g4 + 4)  * ROWF4,
        (size_t)(ebase + g4 + 8)  * ROWF4, (size_t)(ebase + g4 + 12) * ROWF4 };

    float t = wid ? 1.f : 0.f;

    #pragma unroll 1
    for (int p = 0; p < NPAIR; ++p) {
        const int b = p & 1;

        // prefetch digit 2p+1 (same buffer, already resident)
        #pragma unroll
        for (int w = 0; w < 4; ++w) {
            A2[w] = sin[b][ln][4 + w];
            C2[w] = sin[b][32 + ln][4 + w];
        }

        // compute digit 2p (registers ready since last iteration)
        if (wid == 0) digit_math<0>(A1, C1, t, &sou[0][ln][0]);
        else          digit_math<1>(A1, C1, t, &sou[1][ln][0]);

        if (p < NPAIR - 1) {
            asm volatile("cp.async.wait_group 0;\n" ::);  // pair p+1 landed
            __syncthreads();                              // visible to all
            // prefetch digit 2p+2 from the other buffer
            #pragma unroll
            for (int w = 0; w < 4; ++w) {
                A1[w] = sin[b ^ 1][ln][w];
                C1[w] = sin[b ^ 1][32 + ln][w];
            }
            // restage this buffer with pair p+2 (all reads of it issued above)
            if (p + 2 < NPAIR) STAGE(b, p + 2);
        }

        // compute digit 2p+1
        if (wid == 0) digit_math<0>(A2, C2, t, &sou[0][ln][4]);
        else          digit_math<1>(A2, C2, t, &sou[1][ln][4]);
        __syncwarp();

        // full-128B coalesced stores of both digits (8 slots)
        const size_t po = (size_t)p * 8 + q4;
        #pragma unroll
        for (int r = 0; r < 4; ++r) {
            optr[obase[r] + po]                      = sou[wid][g4 + 4 * r][q4];
            optr[obase[r] + (size_t)16 * ROWF4 + po] = sou[wid][g4 + 4 * r + 16][q4];
        }
        __syncwarp();   // sou reads done before next iteration overwrites
    }
    #undef STAGE
}

extern "C" void kernel_launch(void* const* d_in, const int* in_sizes, int n_in,
                              void* d_out, int out_size)
{
    const float4* op1 = (const float4*)d_in[0];
    const float4* op2 = (const float4*)d_in[1];
    float* out = (float*)d_out;
    float4* outa = (float4*)out;
    float4* outs = (float4*)(out + (size_t)BB * LL * KK);

    bitop_kernel<<<BB / 32, 64>>>(op1, op2, outa, outs);
}